// round 1
// baseline (speedup 1.0000x reference)
#include <cuda_runtime.h>
#include <cuda_bf16.h>
#include <math.h>

// ---------------- problem constants ----------------
#define V_  32000
#define D_  512
#define L_  6
#define FF_ 2048
#define T_  2048
#define B_  2
#define S_  8
#define DS_ 32
#define K_  15

#define BT_ (B_ * T_)          // 4096 tokens
#define NC_ 32                 // scan chunks
#define TC_ (T_ / NC_)         // 64 steps per chunk

// ---------------- device scratch (no allocations allowed) ----------------
__device__ float d_X  [BT_ * D_];        // residual stream
__device__ float d_HN [BT_ * D_];        // normalized activations
__device__ float d_GV [BT_ * 2 * D_];    // mixer_up output (gate | val)
__device__ float d_CG [BT_ * D_];        // conv(val) * sigmoid(gate)
__device__ float d_G  [BT_ * S_];        // write gates (sigmoid applied)
__device__ float d_RQ [BT_ * S_];        // read-query logits
__device__ float d_V  [BT_ * DS_];       // write values
__device__ float d_MS [BT_ * S_ * DS_];  // mem_stack
__device__ float d_RF [BT_ * S_ * DS_];  // softmax-weighted read features
__device__ float d_UPa[BT_ * FF_];       // FFN gate branch / fused up
__device__ float d_UPb[BT_ * FF_];       // FFN up branch
__device__ float d_MEM[B_ * S_ * DS_];   // carried memory across layers
__device__ float d_CHA[B_ * S_ * NC_];           // chunk A products
__device__ float d_CHB[B_ * S_ * DS_ * NC_];     // chunk B compositions
__device__ float d_CST[B_ * S_ * DS_ * NC_];     // chunk start states

// ---------------- GEMM: C[M,N] = A[M,K] @ W[N,K]^T (+ residual) ----------------
// Classic 128x128x8 shared-memory tile, 256 threads, 8x8 microtile.
// All M,N multiples of 128 and K multiples of 8 in this model.
template<bool RES>
__global__ __launch_bounds__(256) void sgemm_kernel(
    const float* __restrict__ A, const float* __restrict__ W,
    const float* __restrict__ R, float* __restrict__ C,
    int M, int N, int K)
{
    __shared__ float As[8][128];
    __shared__ float Ws[8][128];

    const int tid = threadIdx.x;
    const int bx = blockIdx.x, by = blockIdx.y;
    const int tx = tid & 15, ty = tid >> 4;

    const int lr = tid >> 1;          // 0..127
    const int lc = (tid & 1) * 4;     // 0 or 4

    const float* Ag = A + (size_t)(by * 128 + lr) * K + lc;
    const float* Wg = W + (size_t)(bx * 128 + lr) * K + lc;

    float acc[8][8];
#pragma unroll
    for (int i = 0; i < 8; i++)
#pragma unroll
        for (int j = 0; j < 8; j++) acc[i][j] = 0.f;

    for (int k0 = 0; k0 < K; k0 += 8) {
        float4 av = *reinterpret_cast<const float4*>(Ag + k0);
        float4 wv = *reinterpret_cast<const float4*>(Wg + k0);
        As[lc + 0][lr] = av.x; As[lc + 1][lr] = av.y;
        As[lc + 2][lr] = av.z; As[lc + 3][lr] = av.w;
        Ws[lc + 0][lr] = wv.x; Ws[lc + 1][lr] = wv.y;
        Ws[lc + 2][lr] = wv.z; Ws[lc + 3][lr] = wv.w;
        __syncthreads();

#pragma unroll
        for (int k = 0; k < 8; k++) {
            float ar[8], br[8];
#pragma unroll
            for (int i = 0; i < 8; i++) ar[i] = As[k][ty * 8 + i];
#pragma unroll
            for (int j = 0; j < 8; j++) br[j] = Ws[k][tx * 8 + j];
#pragma unroll
            for (int i = 0; i < 8; i++)
#pragma unroll
                for (int j = 0; j < 8; j++)
                    acc[i][j] += ar[i] * br[j];
        }
        __syncthreads();
    }

    const int row0 = by * 128 + ty * 8;
    const int col0 = bx * 128 + tx * 8;
#pragma unroll
    for (int i = 0; i < 8; i++) {
        size_t base = (size_t)(row0 + i) * N + col0;
#pragma unroll
        for (int j = 0; j < 8; j += 4) {
            float4 v;
            v.x = acc[i][j + 0]; v.y = acc[i][j + 1];
            v.z = acc[i][j + 2]; v.w = acc[i][j + 3];
            if (RES) {
                float4 r = *reinterpret_cast<const float4*>(R + base + j);
                v.x += r.x; v.y += r.y; v.z += r.z; v.w += r.w;
            }
            *reinterpret_cast<float4*>(C + base + j) = v;
        }
    }
}

// ---------------- embed gather + rmsnorm(ln_in) ----------------
__global__ __launch_bounds__(256) void embed_norm_kernel(
    const int* __restrict__ tokens, const float* __restrict__ embed,
    const float* __restrict__ w, float* __restrict__ out)
{
    const int bt = blockIdx.x;
    const int tid = threadIdx.x;
    const int tok = tokens[bt];
    const float* row = embed + (size_t)tok * D_;
    float x0 = row[tid], x1 = row[tid + 256];
    __shared__ float red[256];
    red[tid] = x0 * x0 + x1 * x1;
    __syncthreads();
    for (int s = 128; s > 0; s >>= 1) {
        if (tid < s) red[tid] += red[tid + s];
        __syncthreads();
    }
    float scale = rsqrtf(red[0] / (float)D_ + 1e-6f);
    out[bt * D_ + tid]       = x0 * scale * w[tid];
    out[bt * D_ + tid + 256] = x1 * scale * w[tid + 256];
}

// ---------------- rmsnorm ----------------
__global__ __launch_bounds__(256) void rmsnorm_kernel(
    const float* __restrict__ X, const float* __restrict__ w, float* __restrict__ O)
{
    const int bt = blockIdx.x;
    const int tid = threadIdx.x;
    float x0 = X[bt * D_ + tid], x1 = X[bt * D_ + tid + 256];
    __shared__ float red[256];
    red[tid] = x0 * x0 + x1 * x1;
    __syncthreads();
    for (int s = 128; s > 0; s >>= 1) {
        if (tid < s) red[tid] += red[tid + s];
        __syncthreads();
    }
    float scale = rsqrtf(red[0] / (float)D_ + 1e-6f);
    O[bt * D_ + tid]       = x0 * scale * w[tid];
    O[bt * D_ + tid + 256] = x1 * scale * w[tid + 256];
}

// ---------------- causal depthwise conv + gate ----------------
__global__ __launch_bounds__(256) void conv_gate_kernel(
    const float* __restrict__ GV, const float* __restrict__ cw, float* __restrict__ CG)
{
    const int idx = blockIdx.x * 256 + threadIdx.x;   // over BT_*D_
    const int d = idx % D_;
    const int bt = idx / D_;
    const int b = bt / T_, t = bt % T_;
    float s = 0.f;
#pragma unroll
    for (int j = 0; j < K_; j++) {
        int tt = t - (K_ - 1) + j;
        if (tt >= 0)
            s += GV[((size_t)(b * T_ + tt) * 2 * D_) + D_ + d] * cw[d * K_ + j];
    }
    float gr = GV[(size_t)bt * 2 * D_ + d];
    CG[idx] = s * (1.f / (1.f + expf(-gr)));
}

// ---------------- small projections: g (sigmoid), rq logits, v ----------------
__global__ __launch_bounds__(256) void smallproj_kernel(
    const float* __restrict__ HN, const float* __restrict__ wg,
    const float* __restrict__ rqw, const float* __restrict__ wv,
    float* __restrict__ G, float* __restrict__ RQ, float* __restrict__ Vv)
{
    const int bt = blockIdx.x;
    const int tid = threadIdx.x;
    __shared__ float h[D_];
    h[tid] = HN[bt * D_ + tid];
    h[tid + 256] = HN[bt * D_ + tid + 256];
    __syncthreads();
    const int warp = tid >> 5, lane = tid & 31;
    for (int o = warp; o < S_ + S_ + DS_; o += 8) {
        const float* wrow;
        if (o < S_) wrow = wg + o * D_;
        else if (o < 2 * S_) wrow = rqw + (o - S_) * D_;
        else wrow = wv + (o - 2 * S_) * D_;
        float s = 0.f;
#pragma unroll
        for (int k = lane; k < D_; k += 32) s += h[k] * wrow[k];
#pragma unroll
        for (int off = 16; off > 0; off >>= 1) s += __shfl_down_sync(0xffffffffu, s, off);
        if (lane == 0) {
            if (o < S_) G[bt * S_ + o] = 1.f / (1.f + expf(-s));
            else if (o < 2 * S_) RQ[bt * S_ + (o - S_)] = s;
            else Vv[bt * DS_ + (o - 2 * S_)] = s;
        }
    }
}

// ---------------- chunked linear-recurrence scan ----------------
// m_t = (1-g_t) * m_{t-1} + g_t * v_t   per (b, s, ds)
__global__ __launch_bounds__(256) void scan_pass1_kernel(
    const float* __restrict__ G, const float* __restrict__ Vv,
    float* __restrict__ CHA, float* __restrict__ CHB)
{
    const int idx = blockIdx.x * 256 + threadIdx.x;   // B_*S_*DS_*NC_
    const int ds = idx % DS_;
    const int s  = (idx / DS_) % S_;
    const int c  = (idx / (DS_ * S_)) % NC_;
    const int b  = idx / (DS_ * S_ * NC_);
    float A = 1.f, Bv = 0.f;
    const int t0 = c * TC_;
    for (int t = t0; t < t0 + TC_; t++) {
        float g = G[(size_t)(b * T_ + t) * S_ + s];
        float a = 1.f - g;
        float bb = g * Vv[(size_t)(b * T_ + t) * DS_ + ds];
        A = a * A;
        Bv = a * Bv + bb;
    }
    CHB[((size_t)(b * S_ + s) * DS_ + ds) * NC_ + c] = Bv;
    if (ds == 0) CHA[(size_t)(b * S_ + s) * NC_ + c] = A;
}

__global__ __launch_bounds__(512) void scan_pass2_kernel(
    const float* __restrict__ CHA, const float* __restrict__ CHB,
    float* __restrict__ MEM, float* __restrict__ CST)
{
    const int idx = threadIdx.x;   // B_*S_*DS_ = 512
    const int ds = idx % DS_;
    const int s  = (idx / DS_) % S_;
    const int b  = idx / (DS_ * S_);
    float st = MEM[idx];
    for (int c = 0; c < NC_; c++) {
        CST[((size_t)(b * S_ + s) * DS_ + ds) * NC_ + c] = st;
        float A = CHA[(size_t)(b * S_ + s) * NC_ + c];
        float Bv = CHB[((size_t)(b * S_ + s) * DS_ + ds) * NC_ + c];
        st = A * st + Bv;
    }
    MEM[idx] = st;   // carried memory for next layer
}

__global__ __launch_bounds__(256) void scan_pass3_kernel(
    const float* __restrict__ G, const float* __restrict__ Vv,
    const float* __restrict__ CST, float* __restrict__ MS)
{
    const int idx = blockIdx.x * 256 + threadIdx.x;
    const int ds = idx % DS_;
    const int s  = (idx / DS_) % S_;
    const int c  = (idx / (DS_ * S_)) % NC_;
    const int b  = idx / (DS_ * S_ * NC_);
    float m = CST[((size_t)(b * S_ + s) * DS_ + ds) * NC_ + c];
    const int t0 = c * TC_;
    for (int t = t0; t < t0 + TC_; t++) {
        float g = G[(size_t)(b * T_ + t) * S_ + s];
        float bb = g * Vv[(size_t)(b * T_ + t) * DS_ + ds];
        m = (1.f - g) * m + bb;
        MS[(size_t)(b * T_ + t) * (S_ * DS_) + s * DS_ + ds] = m;
    }
}

// ---------------- softmax read-weights * mem_stack ----------------
__global__ __launch_bounds__(256) void rf_kernel(
    const float* __restrict__ RQ, const float* __restrict__ MS, float* __restrict__ RF)
{
    const int bt = blockIdx.x;
    const int tid = threadIdx.x;   // 256 = S_*DS_
    __shared__ float q[S_];
    if (tid < S_) q[tid] = RQ[bt * S_ + tid];
    __syncthreads();
    float mx = q[0];
#pragma unroll
    for (int i = 1; i < S_; i++) mx = fmaxf(mx, q[i]);
    float denom = 0.f;
#pragma unroll
    for (int i = 0; i < S_; i++) denom += expf(q[i] - mx);
    const int s = tid >> 5;
    float w = expf(q[s] - mx) / denom;
    RF[(size_t)bt * 256 + tid] = w * MS[(size_t)bt * 256 + tid];
}

// ---------------- silu(a) * b ----------------
__global__ __launch_bounds__(256) void silu_mul_kernel(float* __restrict__ Aa, const float* __restrict__ Bb)
{
    const size_t i = (size_t)blockIdx.x * 256 + threadIdx.x;
    float a = Aa[i];
    Aa[i] = (a / (1.f + expf(-a))) * Bb[i];
}

// ---------------- zero memory ----------------
__global__ void zero_mem_kernel(float* __restrict__ M)
{
    M[threadIdx.x] = 0.f;
}

// ---------------- host orchestration ----------------
static void* devptr(const void* symbol) {
    void* p = nullptr;
    cudaGetSymbolAddress(&p, symbol);
    return p;
}

extern "C" void kernel_launch(void* const* d_in, const int* in_sizes, int n_in,
                              void* d_out, int out_size)
{
    const int*   tokens    = (const int*)  d_in[0];
    const float* embed     = (const float*)d_in[1];
    const float* ln_in     = (const float*)d_in[2];
    const float* ln1       = (const float*)d_in[3];
    const float* mixer_up  = (const float*)d_in[4];
    const float* conv_w    = (const float*)d_in[5];
    const float* mixer_down= (const float*)d_in[6];
    const float* ln_mem    = (const float*)d_in[7];
    const float* wg        = (const float*)d_in[8];
    const float* wv        = (const float*)d_in[9];
    const float* rq        = (const float*)d_in[10];
    const float* ro        = (const float*)d_in[11];
    const float* ln2       = (const float*)d_in[12];
    const float* Wgf       = (const float*)d_in[13];
    const float* Wuf       = (const float*)d_in[14];
    const float* Wof       = (const float*)d_in[15];
    const float* ln_out    = (const float*)d_in[16];
    float* out = (float*)d_out;

    float* X   = (float*)devptr(d_X);
    float* HN  = (float*)devptr(d_HN);
    float* GV  = (float*)devptr(d_GV);
    float* CG  = (float*)devptr(d_CG);
    float* G   = (float*)devptr(d_G);
    float* RQ  = (float*)devptr(d_RQ);
    float* Vv  = (float*)devptr(d_V);
    float* MS  = (float*)devptr(d_MS);
    float* RF  = (float*)devptr(d_RF);
    float* UPa = (float*)devptr(d_UPa);
    float* UPb = (float*)devptr(d_UPb);
    float* MEM = (float*)devptr(d_MEM);
    float* CHA = (float*)devptr(d_CHA);
    float* CHB = (float*)devptr(d_CHB);
    float* CST = (float*)devptr(d_CST);

    const int scanThreads = B_ * S_ * DS_ * NC_;   // 16384

    zero_mem_kernel<<<1, B_ * S_ * DS_>>>(MEM);
    embed_norm_kernel<<<BT_, 256>>>(tokens, embed, ln_in, X);

    for (int i = 0; i < L_; i++) {
        const float* ln1_i = ln1 + i * D_;
        const float* mu_i  = mixer_up + (size_t)i * 2 * D_ * D_;
        const float* cw_i  = conv_w + (size_t)i * D_ * K_;
        const float* md_i  = mixer_down + (size_t)i * D_ * D_;
        const float* lnm_i = ln_mem + i * D_;
        const float* wg_i  = wg + (size_t)i * S_ * D_;
        const float* wv_i  = wv + (size_t)i * DS_ * D_;
        const float* rq_i  = rq + (size_t)i * S_ * D_;
        const float* ro_i  = ro + (size_t)i * D_ * S_ * DS_;
        const float* ln2_i = ln2 + i * D_;
        const float* Wgf_i = Wgf + (size_t)i * FF_ * D_;
        const float* Wuf_i = Wuf + (size_t)i * FF_ * D_;
        const float* Wof_i = Wof + (size_t)i * D_ * FF_;

        // mixer branch
        rmsnorm_kernel<<<BT_, 256>>>(X, ln1_i, HN);
        sgemm_kernel<false><<<dim3(2 * D_ / 128, BT_ / 128), 256>>>(
            HN, mu_i, nullptr, GV, BT_, 2 * D_, D_);
        conv_gate_kernel<<<BT_ * D_ / 256, 256>>>(GV, cw_i, CG);
        sgemm_kernel<true><<<dim3(D_ / 128, BT_ / 128), 256>>>(
            CG, md_i, X, X, BT_, D_, D_);

        // story memory branch
        rmsnorm_kernel<<<BT_, 256>>>(X, lnm_i, HN);
        smallproj_kernel<<<BT_, 256>>>(HN, wg_i, rq_i, wv_i, G, RQ, Vv);
        scan_pass1_kernel<<<scanThreads / 256, 256>>>(G, Vv, CHA, CHB);
        scan_pass2_kernel<<<1, B_ * S_ * DS_>>>(CHA, CHB, MEM, CST);
        scan_pass3_kernel<<<scanThreads / 256, 256>>>(G, Vv, CST, MS);
        rf_kernel<<<BT_, 256>>>(RQ, MS, RF);
        sgemm_kernel<true><<<dim3(D_ / 128, BT_ / 128), 256>>>(
            RF, ro_i, X, X, BT_, D_, S_ * DS_);

        // FFN branch
        rmsnorm_kernel<<<BT_, 256>>>(X, ln2_i, HN);
        sgemm_kernel<false><<<dim3(FF_ / 128, BT_ / 128), 256>>>(
            HN, Wgf_i, nullptr, UPa, BT_, FF_, D_);
        sgemm_kernel<false><<<dim3(FF_ / 128, BT_ / 128), 256>>>(
            HN, Wuf_i, nullptr, UPb, BT_, FF_, D_);
        silu_mul_kernel<<<(int)((size_t)BT_ * FF_ / 256), 256>>>(UPa, UPb);
        sgemm_kernel<true><<<dim3(D_ / 128, BT_ / 128), 256>>>(
            UPa, Wof_i, X, X, BT_, D_, FF_);
    }

    // tied head
    rmsnorm_kernel<<<BT_, 256>>>(X, ln_out, HN);
    sgemm_kernel<false><<<dim3(V_ / 128, BT_ / 128), 256>>>(
        HN, embed, nullptr, out, BT_, V_, D_);
}

// round 3
// speedup vs baseline: 2.6254x; 2.6254x over previous
#include <cuda_runtime.h>
#include <cuda_bf16.h>
#include <stdint.h>
#include <math.h>

// ---------------- problem constants ----------------
#define V_  32000
#define D_  512
#define L_  6
#define FF_ 2048
#define T_  2048
#define B_  2
#define S_  8
#define DS_ 32
#define K_  15

#define BT_ (B_ * T_)          // 4096 tokens
#define NC_ 32                 // scan chunks
#define TC_ (T_ / NC_)         // 64 steps per chunk

// ---------------- device scratch (no allocations allowed) ----------------
__device__ float d_X  [BT_ * D_];
__device__ float d_HN [BT_ * D_];
__device__ float d_GV [BT_ * 2 * D_];
__device__ float d_CG [BT_ * D_];
__device__ float d_G  [BT_ * S_];
__device__ float d_RQ [BT_ * S_];
__device__ float d_V  [BT_ * DS_];
__device__ float d_MS [BT_ * S_ * DS_];
__device__ float d_RF [BT_ * S_ * DS_];
__device__ float d_UPa[BT_ * FF_];
__device__ float d_UPb[BT_ * FF_];
__device__ float d_MEM[B_ * S_ * DS_];
__device__ float d_CHA[B_ * S_ * NC_];
__device__ float d_CHB[B_ * S_ * DS_ * NC_];
__device__ float d_CST[B_ * S_ * DS_ * NC_];

// ---------------- tf32 helpers ----------------
__device__ __forceinline__ unsigned int f2tf(float f) {
    unsigned int u;
    asm("cvt.rna.tf32.f32 %0, %1;" : "=r"(u) : "f"(f));
    return u;
}

__device__ __forceinline__ void mma_tf32(float* c, const unsigned int* a, const unsigned int* b) {
    asm volatile(
        "mma.sync.aligned.m16n8k8.row.col.f32.tf32.tf32.f32 "
        "{%0,%1,%2,%3}, {%4,%5,%6,%7}, {%8,%9}, {%0,%1,%2,%3};"
        : "+f"(c[0]), "+f"(c[1]), "+f"(c[2]), "+f"(c[3])
        : "r"(a[0]), "r"(a[1]), "r"(a[2]), "r"(a[3]), "r"(b[0]), "r"(b[1]));
}

// ---------------- tensor-core GEMM: C[M,N] = A[M,K] @ W[N,K]^T (+R) ----------------
// 128x128 block tile, 8 warps (2x4), 64x32 warp tile, k-step 16.
// Requires: M%128==0, N%128==0, K%16==0, pointers 16B aligned.
#define PAD_ 20   // k-stride in smem words; (20*g + k) mod 32 is a permutation -> conflict-free
template<bool RES>
__global__ __launch_bounds__(256) void tfgemm_kernel(
    const float* __restrict__ A, const float* __restrict__ W,
    const float* __restrict__ R, float* __restrict__ C,
    int M, int N, int K)
{
    __shared__ unsigned int As[128 * PAD_];
    __shared__ unsigned int Bs[128 * PAD_];

    const int tid  = threadIdx.x;
    const int wid  = tid >> 5;
    const int lane = tid & 31;
    const int grp  = lane >> 2;   // 0..7
    const int kin  = lane & 3;    // 0..3
    const int wm   = (wid & 1) * 64;
    const int wn   = (wid >> 1) * 32;

    const int lr  = tid >> 2;         // 0..63
    const int lc4 = (tid & 3) * 4;    // 0,4,8,12

    const float* Ag  = A + (size_t)(blockIdx.y * 128 + lr) * K + lc4;
    const float* Ag2 = Ag + (size_t)64 * K;
    const float* Wg  = W + (size_t)(blockIdx.x * 128 + lr) * K + lc4;
    const float* Wg2 = Wg + (size_t)64 * K;

    float acc[4][4][4];
#pragma unroll
    for (int i = 0; i < 4; i++)
#pragma unroll
        for (int j = 0; j < 4; j++)
#pragma unroll
            for (int r = 0; r < 4; r++) acc[i][j][r] = 0.f;

    // prologue: tile 0 -> smem (tf32-rounded)
    {
        float4 a0 = *reinterpret_cast<const float4*>(Ag);
        float4 a1 = *reinterpret_cast<const float4*>(Ag2);
        float4 b0 = *reinterpret_cast<const float4*>(Wg);
        float4 b1 = *reinterpret_cast<const float4*>(Wg2);
        uint4* pa0 = reinterpret_cast<uint4*>(&As[lr * PAD_ + lc4]);
        uint4* pa1 = reinterpret_cast<uint4*>(&As[(lr + 64) * PAD_ + lc4]);
        uint4* pb0 = reinterpret_cast<uint4*>(&Bs[lr * PAD_ + lc4]);
        uint4* pb1 = reinterpret_cast<uint4*>(&Bs[(lr + 64) * PAD_ + lc4]);
        *pa0 = make_uint4(f2tf(a0.x), f2tf(a0.y), f2tf(a0.z), f2tf(a0.w));
        *pa1 = make_uint4(f2tf(a1.x), f2tf(a1.y), f2tf(a1.z), f2tf(a1.w));
        *pb0 = make_uint4(f2tf(b0.x), f2tf(b0.y), f2tf(b0.z), f2tf(b0.w));
        *pb1 = make_uint4(f2tf(b1.x), f2tf(b1.y), f2tf(b1.z), f2tf(b1.w));
    }
    __syncthreads();

    for (int k0 = 16; k0 <= K; k0 += 16) {
        const bool more = (k0 < K);
        float4 na0, na1, nb0, nb1;
        if (more) {
            na0 = *reinterpret_cast<const float4*>(Ag  + k0);
            na1 = *reinterpret_cast<const float4*>(Ag2 + k0);
            nb0 = *reinterpret_cast<const float4*>(Wg  + k0);
            nb1 = *reinterpret_cast<const float4*>(Wg2 + k0);
        }

#pragma unroll
        for (int s = 0; s < 2; s++) {
            unsigned int af[4][4], bf[4][2];
            const int kc = s * 8 + kin;
#pragma unroll
            for (int i = 0; i < 4; i++) {
                const int row = wm + i * 16 + grp;
                af[i][0] = As[row * PAD_ + kc];
                af[i][1] = As[(row + 8) * PAD_ + kc];
                af[i][2] = As[row * PAD_ + kc + 4];
                af[i][3] = As[(row + 8) * PAD_ + kc + 4];
            }
#pragma unroll
            for (int j = 0; j < 4; j++) {
                const int n = wn + j * 8 + grp;
                bf[j][0] = Bs[n * PAD_ + kc];
                bf[j][1] = Bs[n * PAD_ + kc + 4];
            }
#pragma unroll
            for (int i = 0; i < 4; i++)
#pragma unroll
                for (int j = 0; j < 4; j++)
                    mma_tf32(acc[i][j], af[i], bf[j]);
        }
        __syncthreads();
        if (more) {
            uint4* pa0 = reinterpret_cast<uint4*>(&As[lr * PAD_ + lc4]);
            uint4* pa1 = reinterpret_cast<uint4*>(&As[(lr + 64) * PAD_ + lc4]);
            uint4* pb0 = reinterpret_cast<uint4*>(&Bs[lr * PAD_ + lc4]);
            uint4* pb1 = reinterpret_cast<uint4*>(&Bs[(lr + 64) * PAD_ + lc4]);
            *pa0 = make_uint4(f2tf(na0.x), f2tf(na0.y), f2tf(na0.z), f2tf(na0.w));
            *pa1 = make_uint4(f2tf(na1.x), f2tf(na1.y), f2tf(na1.z), f2tf(na1.w));
            *pb0 = make_uint4(f2tf(nb0.x), f2tf(nb0.y), f2tf(nb0.z), f2tf(nb0.w));
            *pb1 = make_uint4(f2tf(nb1.x), f2tf(nb1.y), f2tf(nb1.z), f2tf(nb1.w));
            __syncthreads();
        }
    }

    // epilogue
    const int row0 = blockIdx.y * 128 + wm + grp;
    const int col0 = blockIdx.x * 128 + wn + 2 * kin;
#pragma unroll
    for (int i = 0; i < 4; i++) {
#pragma unroll
        for (int j = 0; j < 4; j++) {
            const size_t o0 = (size_t)(row0 + i * 16) * N + col0 + j * 8;
            const size_t o1 = (size_t)(row0 + i * 16 + 8) * N + col0 + j * 8;
            float2 v0 = make_float2(acc[i][j][0], acc[i][j][1]);
            float2 v1 = make_float2(acc[i][j][2], acc[i][j][3]);
            if (RES) {
                float2 r0 = *reinterpret_cast<const float2*>(R + o0);
                float2 r1 = *reinterpret_cast<const float2*>(R + o1);
                v0.x += r0.x; v0.y += r0.y;
                v1.x += r1.x; v1.y += r1.y;
            }
            *reinterpret_cast<float2*>(C + o0) = v0;
            *reinterpret_cast<float2*>(C + o1) = v1;
        }
    }
}

// ---------------- embed gather + rmsnorm(ln_in) ----------------
__global__ __launch_bounds__(256) void embed_norm_kernel(
    const int* __restrict__ tokens, const float* __restrict__ embed,
    const float* __restrict__ w, float* __restrict__ out)
{
    const int bt = blockIdx.x;
    const int tid = threadIdx.x;
    const int tok = tokens[bt];
    const float* row = embed + (size_t)tok * D_;
    float x0 = row[tid], x1 = row[tid + 256];
    __shared__ float red[256];
    red[tid] = x0 * x0 + x1 * x1;
    __syncthreads();
    for (int s = 128; s > 0; s >>= 1) {
        if (tid < s) red[tid] += red[tid + s];
        __syncthreads();
    }
    float scale = rsqrtf(red[0] / (float)D_ + 1e-6f);
    out[bt * D_ + tid]       = x0 * scale * w[tid];
    out[bt * D_ + tid + 256] = x1 * scale * w[tid + 256];
}

// ---------------- rmsnorm ----------------
__global__ __launch_bounds__(256) void rmsnorm_kernel(
    const float* __restrict__ X, const float* __restrict__ w, float* __restrict__ O)
{
    const int bt = blockIdx.x;
    const int tid = threadIdx.x;
    float x0 = X[bt * D_ + tid], x1 = X[bt * D_ + tid + 256];
    __shared__ float red[256];
    red[tid] = x0 * x0 + x1 * x1;
    __syncthreads();
    for (int s = 128; s > 0; s >>= 1) {
        if (tid < s) red[tid] += red[tid + s];
        __syncthreads();
    }
    float scale = rsqrtf(red[0] / (float)D_ + 1e-6f);
    O[bt * D_ + tid]       = x0 * scale * w[tid];
    O[bt * D_ + tid + 256] = x1 * scale * w[tid + 256];
}

// ---------------- causal depthwise conv + gate ----------------
__global__ __launch_bounds__(256) void conv_gate_kernel(
    const float* __restrict__ GV, const float* __restrict__ cw, float* __restrict__ CG)
{
    const int idx = blockIdx.x * 256 + threadIdx.x;
    const int d = idx % D_;
    const int bt = idx / D_;
    const int b = bt / T_, t = bt % T_;
    float s = 0.f;
#pragma unroll
    for (int j = 0; j < K_; j++) {
        int tt = t - (K_ - 1) + j;
        if (tt >= 0)
            s += GV[((size_t)(b * T_ + tt) * 2 * D_) + D_ + d] * cw[d * K_ + j];
    }
    float gr = GV[(size_t)bt * 2 * D_ + d];
    CG[idx] = s * (1.f / (1.f + expf(-gr)));
}

// ---------------- small projections: g (sigmoid), rq logits, v ----------------
__global__ __launch_bounds__(256) void smallproj_kernel(
    const float* __restrict__ HN, const float* __restrict__ wg,
    const float* __restrict__ rqw, const float* __restrict__ wv,
    float* __restrict__ G, float* __restrict__ RQ, float* __restrict__ Vv)
{
    const int bt = blockIdx.x;
    const int tid = threadIdx.x;
    __shared__ float h[D_];
    h[tid] = HN[bt * D_ + tid];
    h[tid + 256] = HN[bt * D_ + tid + 256];
    __syncthreads();
    const int warp = tid >> 5, lane = tid & 31;
    for (int o = warp; o < S_ + S_ + DS_; o += 8) {
        const float* wrow;
        if (o < S_) wrow = wg + o * D_;
        else if (o < 2 * S_) wrow = rqw + (o - S_) * D_;
        else wrow = wv + (o - 2 * S_) * D_;
        float s = 0.f;
#pragma unroll
        for (int k = lane; k < D_; k += 32) s += h[k] * wrow[k];
#pragma unroll
        for (int off = 16; off > 0; off >>= 1) s += __shfl_down_sync(0xffffffffu, s, off);
        if (lane == 0) {
            if (o < S_) G[bt * S_ + o] = 1.f / (1.f + expf(-s));
            else if (o < 2 * S_) RQ[bt * S_ + (o - S_)] = s;
            else Vv[bt * DS_ + (o - 2 * S_)] = s;
        }
    }
}

// ---------------- chunked linear-recurrence scan ----------------
__global__ __launch_bounds__(256) void scan_pass1_kernel(
    const float* __restrict__ G, const float* __restrict__ Vv,
    float* __restrict__ CHA, float* __restrict__ CHB)
{
    const int idx = blockIdx.x * 256 + threadIdx.x;
    const int ds = idx % DS_;
    const int s  = (idx / DS_) % S_;
    const int c  = (idx / (DS_ * S_)) % NC_;
    const int b  = idx / (DS_ * S_ * NC_);
    float A = 1.f, Bv = 0.f;
    const int t0 = c * TC_;
    for (int t = t0; t < t0 + TC_; t++) {
        float g = G[(size_t)(b * T_ + t) * S_ + s];
        float a = 1.f - g;
        float bb = g * Vv[(size_t)(b * T_ + t) * DS_ + ds];
        A = a * A;
        Bv = a * Bv + bb;
    }
    CHB[((size_t)(b * S_ + s) * DS_ + ds) * NC_ + c] = Bv;
    if (ds == 0) CHA[(size_t)(b * S_ + s) * NC_ + c] = A;
}

__global__ __launch_bounds__(512) void scan_pass2_kernel(
    const float* __restrict__ CHA, const float* __restrict__ CHB,
    float* __restrict__ MEM, float* __restrict__ CST)
{
    const int idx = threadIdx.x;
    const int ds = idx % DS_;
    const int s  = (idx / DS_) % S_;
    const int b  = idx / (DS_ * S_);
    float st = MEM[idx];
    for (int c = 0; c < NC_; c++) {
        CST[((size_t)(b * S_ + s) * DS_ + ds) * NC_ + c] = st;
        float A = CHA[(size_t)(b * S_ + s) * NC_ + c];
        float Bv = CHB[((size_t)(b * S_ + s) * DS_ + ds) * NC_ + c];
        st = A * st + Bv;
    }
    MEM[idx] = st;
}

__global__ __launch_bounds__(256) void scan_pass3_kernel(
    const float* __restrict__ G, const float* __restrict__ Vv,
    const float* __restrict__ CST, float* __restrict__ MS)
{
    const int idx = blockIdx.x * 256 + threadIdx.x;
    const int ds = idx % DS_;
    const int s  = (idx / DS_) % S_;
    const int c  = (idx / (DS_ * S_)) % NC_;
    const int b  = idx / (DS_ * S_ * NC_);
    float m = CST[((size_t)(b * S_ + s) * DS_ + ds) * NC_ + c];
    const int t0 = c * TC_;
    for (int t = t0; t < t0 + TC_; t++) {
        float g = G[(size_t)(b * T_ + t) * S_ + s];
        float bb = g * Vv[(size_t)(b * T_ + t) * DS_ + ds];
        m = (1.f - g) * m + bb;
        MS[(size_t)(b * T_ + t) * (S_ * DS_) + s * DS_ + ds] = m;
    }
}

// ---------------- softmax read-weights * mem_stack ----------------
__global__ __launch_bounds__(256) void rf_kernel(
    const float* __restrict__ RQ, const float* __restrict__ MS, float* __restrict__ RF)
{
    const int bt = blockIdx.x;
    const int tid = threadIdx.x;
    __shared__ float q[S_];
    if (tid < S_) q[tid] = RQ[bt * S_ + tid];
    __syncthreads();
    float mx = q[0];
#pragma unroll
    for (int i = 1; i < S_; i++) mx = fmaxf(mx, q[i]);
    float denom = 0.f;
#pragma unroll
    for (int i = 0; i < S_; i++) denom += expf(q[i] - mx);
    const int s = tid >> 5;
    float w = expf(q[s] - mx) / denom;
    RF[(size_t)bt * 256 + tid] = w * MS[(size_t)bt * 256 + tid];
}

// ---------------- silu(a) * b ----------------
__global__ __launch_bounds__(256) void silu_mul_kernel(float* __restrict__ Aa, const float* __restrict__ Bb)
{
    const size_t i = (size_t)blockIdx.x * 256 + threadIdx.x;
    float a = Aa[i];
    Aa[i] = (a / (1.f + expf(-a))) * Bb[i];
}

// ---------------- zero memory ----------------
__global__ void zero_mem_kernel(float* __restrict__ M)
{
    M[threadIdx.x] = 0.f;
}

// ---------------- host orchestration ----------------
static void* devptr(const void* symbol) {
    void* p = nullptr;
    cudaGetSymbolAddress(&p, symbol);
    return p;
}

extern "C" void kernel_launch(void* const* d_in, const int* in_sizes, int n_in,
                              void* d_out, int out_size)
{
    const int*   tokens    = (const int*)  d_in[0];
    const float* embed     = (const float*)d_in[1];
    const float* ln_in     = (const float*)d_in[2];
    const float* ln1       = (const float*)d_in[3];
    const float* mixer_up  = (const float*)d_in[4];
    const float* conv_w    = (const float*)d_in[5];
    const float* mixer_down= (const float*)d_in[6];
    const float* ln_mem    = (const float*)d_in[7];
    const float* wg        = (const float*)d_in[8];
    const float* wv        = (const float*)d_in[9];
    const float* rq        = (const float*)d_in[10];
    const float* ro        = (const float*)d_in[11];
    const float* ln2       = (const float*)d_in[12];
    const float* Wgf       = (const float*)d_in[13];
    const float* Wuf       = (const float*)d_in[14];
    const float* Wof       = (const float*)d_in[15];
    const float* ln_out    = (const float*)d_in[16];
    float* out = (float*)d_out;

    float* X   = (float*)devptr(d_X);
    float* HN  = (float*)devptr(d_HN);
    float* GV  = (float*)devptr(d_GV);
    float* CG  = (float*)devptr(d_CG);
    float* G   = (float*)devptr(d_G);
    float* RQ  = (float*)devptr(d_RQ);
    float* Vv  = (float*)devptr(d_V);
    float* MS  = (float*)devptr(d_MS);
    float* RF  = (float*)devptr(d_RF);
    float* UPa = (float*)devptr(d_UPa);
    float* UPb = (float*)devptr(d_UPb);
    float* MEM = (float*)devptr(d_MEM);
    float* CHA = (float*)devptr(d_CHA);
    float* CHB = (float*)devptr(d_CHB);
    float* CST = (float*)devptr(d_CST);

    const int scanThreads = B_ * S_ * DS_ * NC_;   // 16384

    zero_mem_kernel<<<1, B_ * S_ * DS_>>>(MEM);
    embed_norm_kernel<<<BT_, 256>>>(tokens, embed, ln_in, X);

    for (int i = 0; i < L_; i++) {
        const float* ln1_i = ln1 + i * D_;
        const float* mu_i  = mixer_up + (size_t)i * 2 * D_ * D_;
        const float* cw_i  = conv_w + (size_t)i * D_ * K_;
        const float* md_i  = mixer_down + (size_t)i * D_ * D_;
        const float* lnm_i = ln_mem + i * D_;
        const float* wg_i  = wg + (size_t)i * S_ * D_;
        const float* wv_i  = wv + (size_t)i * DS_ * D_;
        const float* rq_i  = rq + (size_t)i * S_ * D_;
        const float* ro_i  = ro + (size_t)i * D_ * S_ * DS_;
        const float* ln2_i = ln2 + i * D_;
        const float* Wgf_i = Wgf + (size_t)i * FF_ * D_;
        const float* Wuf_i = Wuf + (size_t)i * FF_ * D_;
        const float* Wof_i = Wof + (size_t)i * D_ * FF_;

        // mixer branch
        rmsnorm_kernel<<<BT_, 256>>>(X, ln1_i, HN);
        tfgemm_kernel<false><<<dim3(2 * D_ / 128, BT_ / 128), 256>>>(
            HN, mu_i, nullptr, GV, BT_, 2 * D_, D_);
        conv_gate_kernel<<<BT_ * D_ / 256, 256>>>(GV, cw_i, CG);
        tfgemm_kernel<true><<<dim3(D_ / 128, BT_ / 128), 256>>>(
            CG, md_i, X, X, BT_, D_, D_);

        // story memory branch
        rmsnorm_kernel<<<BT_, 256>>>(X, lnm_i, HN);
        smallproj_kernel<<<BT_, 256>>>(HN, wg_i, rq_i, wv_i, G, RQ, Vv);
        scan_pass1_kernel<<<scanThreads / 256, 256>>>(G, Vv, CHA, CHB);
        scan_pass2_kernel<<<1, B_ * S_ * DS_>>>(CHA, CHB, MEM, CST);
        scan_pass3_kernel<<<scanThreads / 256, 256>>>(G, Vv, CST, MS);
        rf_kernel<<<BT_, 256>>>(RQ, MS, RF);
        tfgemm_kernel<true><<<dim3(D_ / 128, BT_ / 128), 256>>>(
            RF, ro_i, X, X, BT_, D_, S_ * DS_);

        // FFN branch
        rmsnorm_kernel<<<BT_, 256>>>(X, ln2_i, HN);
        tfgemm_kernel<false><<<dim3(FF_ / 128, BT_ / 128), 256>>>(
            HN, Wgf_i, nullptr, UPa, BT_, FF_, D_);
        tfgemm_kernel<false><<<dim3(FF_ / 128, BT_ / 128), 256>>>(
            HN, Wuf_i, nullptr, UPb, BT_, FF_, D_);
        silu_mul_kernel<<<(int)((size_t)BT_ * FF_ / 256), 256>>>(UPa, UPb);
        tfgemm_kernel<true><<<dim3(D_ / 128, BT_ / 128), 256>>>(
            UPa, Wof_i, X, X, BT_, D_, FF_);
    }

    // tied head
    rmsnorm_kernel<<<BT_, 256>>>(X, ln_out, HN);
    tfgemm_kernel<false><<<dim3(V_ / 128, BT_ / 128), 256>>>(
        HN, embed, nullptr, out, BT_, V_, D_);
}